// round 5
// baseline (speedup 1.0000x reference)
#include <cuda_runtime.h>
#include <cuda_fp16.h>

// DifferentiableCensus: out = (1/9) * sum_{3x3, edge-clamped} sigmoid(neighbor - center)
// x: (16,3,512,512) f32 -> 48 independent 512x512 images.
//
// Round 5: kill L1tex-queue contention + wave tail.
//  - CTA stages a 512-wide x 34-row tile (prescaled half2) into smem via
//    coalesced float4 LDGs (17/thread, no scattered halo LDGs at all).
//  - Compute = R4's half2 edge-sharing datapath (tanh.approx.f16x2, every
//    pixel-pair edge computed once; reverse term = negation), reading rows
//    from smem. Column clamp handled by clamped smem indices.
//  - 768 CTAs, 5 resident/SM -> ~single wave.

static constexpr int H = 512;
static constexpr int W = 512;
static constexpr int TILE_ROWS = 32;
static constexpr int STAGE_ROWS = TILE_ROWS + 2;       // 34 (1 halo row each side)
static constexpr int BLOCK = 256;
static constexpr int ROWS_PER_THREAD = 16;             // 2 row-bands of 16

__device__ __forceinline__ __half2 tanh_h2(__half2 h) {
    unsigned u = *reinterpret_cast<unsigned*>(&h);
    unsigned r;
    asm("tanh.approx.f16x2 %0, %1;" : "=r"(r) : "r"(u));
    return *reinterpret_cast<__half2*>(&r);
}

__device__ __forceinline__ __half2 prmt(__half2 a, __half2 b, unsigned sel) {
    unsigned r = __byte_perm(*reinterpret_cast<unsigned*>(&a),
                             *reinterpret_cast<unsigned*>(&b), sel);
    return *reinterpret_cast<__half2*>(&r);
}
__device__ __forceinline__ __half2 u2h2(unsigned u) { return *reinterpret_cast<__half2*>(&u); }

__global__ __launch_bounds__(BLOCK, 5)
void census_kernel(const float* __restrict__ x, float* __restrict__ out) {
    __shared__ __half2 sh[STAGE_ROWS * 256];           // 34 rows x 512 halves = 34 KB
    const __half* __restrict__ shh = reinterpret_cast<const __half*>(sh);

    const int tid     = threadIdx.x;
    const int tile_r0 = blockIdx.y * TILE_ROWS;
    const int img     = blockIdx.z;

    const float* __restrict__ xi = x   + (size_t)img * H * W;
    float* __restrict__       oi = out + (size_t)img * H * W;

    // ---- Stage 34 rows x 512 cols as prescaled half2 (fully coalesced) ----
    #pragma unroll
    for (int t = 0; t < (STAGE_ROWS * 128) / BLOCK; t++) {   // 17 iterations
        const int u   = tid + t * BLOCK;
        const int row = u >> 7;                               // 0..33
        const int c4  = u & 127;                              // float4 index
        const int g   = min(max(tile_r0 - 1 + row, 0), H - 1);
        const float4 v = __ldg(reinterpret_cast<const float4*>(xi + (size_t)g * W + c4 * 4));
        sh[row * 256 + c4 * 2]     = __floats2half2_rn(0.5f * v.x, 0.5f * v.y);
        sh[row * 256 + c4 * 2 + 1] = __floats2half2_rn(0.5f * v.z, 0.5f * v.w);
    }
    __syncthreads();

    // ---- Compute: thread owns 4 cols x 16 rows ----
    const int tx   = tid & 127;
    const int ty   = tid >> 7;                                // 0 or 1
    const int c0   = tx * 4;
    const int clh  = max(c0 - 1, 0);                          // clamped halo half-index
    const int crh  = min(c0 + 4, W - 1);
    const int base = ty * ROWS_PER_THREAD;                    // smem row of p at k=0

    // Row reader: m1=(v1,v2), m2=(v3,v4), l=v0 halo, r=v5 halo (all prescaled).
    auto read_row = [&](int sr, __half2& m1, __half2& m2, __half& l, __half& r) {
        const uint2 mm = *reinterpret_cast<const uint2*>(&sh[sr * 256 + tx * 2]);
        m1 = u2h2(mm.x);
        m2 = u2h2(mm.y);
        l  = shh[sr * 512 + clh];
        r  = shh[sr * 512 + crh];
    };

    __half2 pM1, pM2; __half plh, prh;
    read_row(base, pM1, pM2, plh, prh);
    __half2 M1b, M2b; __half bl, br;
    read_row(base + 1, M1b, M2b, bl, br);

    __half2 bB = prmt(M1b, M2b, 0x5432);                      // (v2,v3)
    __half2 bC = __halves2half2(__high2half(M2b), br);        // (v4,v5)
    {
        // Priming carries: S/SE/SW edge tanh of row p.
        __half2 bA = __halves2half2(bl, __low2half(M1b));     // (v0,v1)
        // values set below
    }
    __half2 pSa  = tanh_h2(__hsub2(M1b, pM1)), pSb  = tanh_h2(__hsub2(M2b, pM2));
    __half2 pDRa = tanh_h2(__hsub2(bB,  pM1)), pDRb = tanh_h2(__hsub2(bC,  pM2));
    __half2 bA0  = __halves2half2(bl, __low2half(M1b));
    __half2 pDLa = tanh_h2(__hsub2(bA0, pM1)), pDLb = tanh_h2(__hsub2(bB,  pM2));

    const __half2 zero = __float2half2_rn(0.0f);

    #pragma unroll
    for (int k = 0; k < ROWS_PER_THREAD; k++) {
        const int sr = base + k + 2;                          // smem row of n
        __half2 nM1, nM2; __half nl, nr;
        read_row(sr, nM1, nM2, nl, nr);
        const __half2 nB = prmt(nM1, nM2, 0x5432);
        const __half2 nA = __halves2half2(nl, __low2half(nM1));
        const __half2 nC = __halves2half2(__high2half(nM2), nr);

        // Forward edges (2 tanh per MUFU issue).
        const __half2 Sa  = tanh_h2(__hsub2(nM1, M1b)), Sb  = tanh_h2(__hsub2(nM2, M2b));
        const __half2 DRa = tanh_h2(__hsub2(nB,  M1b)), DRb = tanh_h2(__hsub2(nC,  M2b));
        const __half2 DLa = tanh_h2(__hsub2(nA,  M1b)), DLb = tanh_h2(__hsub2(nB,  M2b));
        const __half2 Ea  = tanh_h2(__hsub2(bB,  M1b)), Eb  = tanh_h2(__hsub2(bC,  M2b));

        // Halo edges: H1 = (W0, UL0), H2 = (UR3, UR3).
        const __half2 H1 = tanh_h2(__hsub2(__halves2half2(bl, plh),
                                           __half2half2(__low2half(M1b))));
        const __half2 H2 = tanh_h2(__hsub2(__half2half2(prh),
                                           __half2half2(__high2half(M2b))));

        // Aligned part: S + DR + DL - pS + E.
        __half2 al1 = __hadd2(__hadd2(Sa, DRa), __hsub2(DLa, pSa));
        __half2 al2 = __hadd2(__hadd2(Sb, DRb), __hsub2(DLb, pSb));
        al1 = __hadd2(al1, Ea);
        al2 = __hadd2(al2, Eb);

        // Misaligned part (lane-realigned with PRMT), as in R4.
        const __half2 sWU = __hadd2(H1, prmt(H1, H1, 0x1032));   // both lanes = W0+UL0
        const __half2 nEa = __hneg2(Ea);
        const __half2 nEb = __hneg2(Eb);
        const __half2 nUR = __hneg2(H2);
        const __half2 Alo = prmt(sWU, nEa, 0x5410);              // (W0+UL0, -E0)
        const __half2 Ahi = prmt(nEa, nEb, 0x5432);              // (-E1, -E2)
        const __half2 Blo = prmt(zero, pDRa, 0x5410);            // (0, pDR0)
        const __half2 Bhi = prmt(pDRa, pDRb, 0x5432);            // (pDR1, pDR2)
        const __half2 Clo = prmt(pDLa, pDLb, 0x5432);            // (pDL1, pDL2)
        const __half2 Chi = prmt(pDLb, nUR, 0x5432);             // (pDL3, -UR3)

        const __half2 Tlo = __hadd2(al1, __hsub2(__hsub2(Alo, Blo), Clo));
        const __half2 Thi = __hadd2(al2, __hsub2(__hsub2(Ahi, Bhi), Chi));

        const float2 lo = __half22float2(Tlo);
        const float2 hi = __half22float2(Thi);
        float4 o;
        o.x = fmaf(lo.x, 1.0f / 18.0f, 0.5f);
        o.y = fmaf(lo.y, 1.0f / 18.0f, 0.5f);
        o.z = fmaf(hi.x, 1.0f / 18.0f, 0.5f);
        o.w = fmaf(hi.y, 1.0f / 18.0f, 0.5f);
        const int r = tile_r0 + ty * ROWS_PER_THREAD + k;
        *reinterpret_cast<float4*>(oi + (size_t)r * W + c0) = o;

        // Roll rows and carries.
        plh = bl; prh = br; bl = nl; br = nr;
        M1b = nM1; M2b = nM2; bB = nB; bC = nC;
        pSa = Sa; pSb = Sb; pDRa = DRa; pDRb = DRb; pDLa = DLa; pDLb = DLb;
    }
}

extern "C" void kernel_launch(void* const* d_in, const int* in_sizes, int n_in,
                              void* d_out, int out_size) {
    (void)in_sizes; (void)n_in; (void)out_size;
    const float* x = (const float*)d_in[0];
    float* out = (float*)d_out;

    dim3 block(BLOCK, 1, 1);
    dim3 grid(1, H / TILE_ROWS, 16 * 3);
    census_kernel<<<grid, block>>>(x, out);
}

// round 6
// speedup vs baseline: 1.0889x; 1.0889x over previous
#include <cuda_runtime.h>
#include <cuda_fp16.h>

// DifferentiableCensus: out = (1/9) * sum_{3x3, edge-clamped} sigmoid(neighbor - center)
// x: (16,3,512,512) f32 -> 48 independent 512x512 images.
//
// Round 6: latency-bound -> shallow strips + front-batched loads.
//  - 1 thread = 4 cols x 4 rows. ALL 6 input rows loaded upfront
//    (6 independent LDG.128 + 12 scalars -> MLP ~18, latency fully overlapped).
//  - half2 SIMD datapath: tanh.approx.f16x2, every pixel-pair edge computed
//    once (reverse term = negation via sigmoid antisymmetry), PRMT realignment.
//  - out = 0.5 + T/18 with T = signed tanh sum; f32 only at load & final FMA.

static constexpr int H = 512;
static constexpr int W = 512;
static constexpr int ROWS_PER_THREAD = 4;
static constexpr int BLOCK_X = 128;            // 128 threads * 4 cols = 512 cols

__device__ __forceinline__ __half2 tanh_h2(__half2 h) {
    unsigned u = *reinterpret_cast<unsigned*>(&h);
    unsigned r;
    asm("tanh.approx.f16x2 %0, %1;" : "=r"(r) : "r"(u));
    return *reinterpret_cast<__half2*>(&r);
}

__device__ __forceinline__ __half2 prmt(__half2 a, __half2 b, unsigned sel) {
    unsigned r = __byte_perm(*reinterpret_cast<unsigned*>(&a),
                             *reinterpret_cast<unsigned*>(&b), sel);
    return *reinterpret_cast<__half2*>(&r);
}
// sel: (a.lo,b.lo)=0x5410  (a.hi,b.lo)=0x5432  swap(a)=0x1032

struct Row { __half2 m1, m2, lr; };   // m1=(v1,v2) m2=(v3,v4) lr=(v0,v5); v0/v5 clamped halos

__global__ __launch_bounds__(BLOCK_X)
void census_kernel(const float* __restrict__ x, float* __restrict__ out) {
    const int c0  = threadIdx.x * 4;
    const int r0  = blockIdx.y * ROWS_PER_THREAD;
    const int img = blockIdx.z;

    const float* __restrict__ xi = x   + (size_t)img * H * W;
    float* __restrict__       oi = out + (size_t)img * H * W;

    const int cl = max(c0 - 1, 0);
    const int cr = min(c0 + 4, W - 1);

    // ---- Front-batched loads: 6 rows, all LDGs independent ----
    float4 m4[6]; float lf[6], rf[6];
    #pragma unroll
    for (int j = 0; j < 6; j++) {
        const int g = min(max(r0 - 1 + j, 0), H - 1);
        const float* row = xi + (size_t)g * W;
        m4[j] = __ldg(reinterpret_cast<const float4*>(row + c0));
        lf[j] = __ldg(row + cl);
        rf[j] = __ldg(row + cr);
    }
    Row rw[6];
    #pragma unroll
    for (int j = 0; j < 6; j++) {
        rw[j].m1 = __floats2half2_rn(0.5f * m4[j].x, 0.5f * m4[j].y);
        rw[j].m2 = __floats2half2_rn(0.5f * m4[j].z, 0.5f * m4[j].w);
        rw[j].lr = __floats2half2_rn(0.5f * lf[j],   0.5f * rf[j]);
    }

    // ---- Priming carries: S/SE/SW edge tanh between rows 0 (p) and 1 (b) ----
    __half2 pSa, pSb, pDRa, pDRb, pDLa, pDLb;
    {
        const Row& p = rw[0];
        const Row& b = rw[1];
        const __half2 bB = prmt(b.m1, b.m2, 0x5432);
        const __half2 bC = __halves2half2(__high2half(b.m2), __high2half(b.lr));
        const __half2 bA = __halves2half2(__low2half(b.lr), __low2half(b.m1));
        pSa  = tanh_h2(__hsub2(b.m1, p.m1)); pSb  = tanh_h2(__hsub2(b.m2, p.m2));
        pDRa = tanh_h2(__hsub2(bB,   p.m1)); pDRb = tanh_h2(__hsub2(bC,   p.m2));
        pDLa = tanh_h2(__hsub2(bA,   p.m1)); pDLb = tanh_h2(__hsub2(bB,   p.m2));
    }

    const __half2 zero = __float2half2_rn(0.0f);

    #pragma unroll
    for (int k = 0; k < ROWS_PER_THREAD; k++) {
        const Row& p = rw[k];
        const Row& b = rw[k + 1];
        const Row& n = rw[k + 2];

        const __half2 nB = prmt(n.m1, n.m2, 0x5432);
        const __half2 nA = __halves2half2(__low2half(n.lr), __low2half(n.m1));
        const __half2 nC = __halves2half2(__high2half(n.m2), __high2half(n.lr));
        const __half2 bB = prmt(b.m1, b.m2, 0x5432);
        const __half2 bC = __halves2half2(__high2half(b.m2), __high2half(b.lr));

        // Forward edges (2 tanh per MUFU issue); centers = b.m1/b.m2.
        const __half2 Sa  = tanh_h2(__hsub2(n.m1, b.m1)), Sb  = tanh_h2(__hsub2(n.m2, b.m2));
        const __half2 DRa = tanh_h2(__hsub2(nB,   b.m1)), DRb = tanh_h2(__hsub2(nC,   b.m2));
        const __half2 DLa = tanh_h2(__hsub2(nA,   b.m1)), DLb = tanh_h2(__hsub2(nB,   b.m2));
        const __half2 Ea  = tanh_h2(__hsub2(bB,   b.m1)), Eb  = tanh_h2(__hsub2(bC,   b.m2));

        // Halo edges: H1 = (W0, UL0), H2 = (UR3, UR3).
        const __half2 H1 = tanh_h2(__hsub2(
            __halves2half2(__low2half(b.lr), __low2half(p.lr)),   // (b0, p0)
            __half2half2(__low2half(b.m1))));                     // (b1, b1)
        const __half2 H2 = tanh_h2(__hsub2(
            __half2half2(__high2half(p.lr)),                      // (p5, p5)
            __half2half2(__high2half(b.m2))));                    // (b4, b4)

        // Aligned part: S + DR + DL - pS + E.
        __half2 al1 = __hadd2(__hadd2(Sa, DRa), __hsub2(DLa, pSa));
        __half2 al2 = __hadd2(__hadd2(Sb, DRb), __hsub2(DLb, pSb));
        al1 = __hadd2(al1, Ea);
        al2 = __hadd2(al2, Eb);

        // Misaligned part (PRMT lane realignment):
        //  (W0+UL0 - pDL1, -E0 - pDR0 - pDL2, -E1 - pDR1 - pDL3, -E2 - pDR2 + UR3)
        const __half2 sWU = __hadd2(H1, prmt(H1, H1, 0x1032));
        const __half2 nEa = __hneg2(Ea);
        const __half2 nEb = __hneg2(Eb);
        const __half2 nUR = __hneg2(H2);
        const __half2 Alo = prmt(sWU, nEa, 0x5410);               // (W0+UL0, -E0)
        const __half2 Ahi = prmt(nEa, nEb, 0x5432);               // (-E1, -E2)
        const __half2 Blo = prmt(zero, pDRa, 0x5410);             // (0, pDR0)
        const __half2 Bhi = prmt(pDRa, pDRb, 0x5432);             // (pDR1, pDR2)
        const __half2 Clo = prmt(pDLa, pDLb, 0x5432);             // (pDL1, pDL2)
        const __half2 Chi = prmt(pDLb, nUR, 0x5432);              // (pDL3, -UR3)

        const __half2 Tlo = __hadd2(al1, __hsub2(__hsub2(Alo, Blo), Clo));
        const __half2 Thi = __hadd2(al2, __hsub2(__hsub2(Ahi, Bhi), Chi));

        const float2 lo = __half22float2(Tlo);
        const float2 hi = __half22float2(Thi);
        float4 o;
        o.x = fmaf(lo.x, 1.0f / 18.0f, 0.5f);
        o.y = fmaf(lo.y, 1.0f / 18.0f, 0.5f);
        o.z = fmaf(hi.x, 1.0f / 18.0f, 0.5f);
        o.w = fmaf(hi.y, 1.0f / 18.0f, 0.5f);
        *reinterpret_cast<float4*>(oi + (size_t)(r0 + k) * W + c0) = o;

        // Carry forward edges as next row's reverse terms.
        pSa = Sa; pSb = Sb; pDRa = DRa; pDRb = DRb; pDLa = DLa; pDLb = DLb;
    }
}

extern "C" void kernel_launch(void* const* d_in, const int* in_sizes, int n_in,
                              void* d_out, int out_size) {
    (void)in_sizes; (void)n_in; (void)out_size;
    const float* x = (const float*)d_in[0];
    float* out = (float*)d_out;

    dim3 block(BLOCK_X, 1, 1);
    dim3 grid(1, H / ROWS_PER_THREAD, 16 * 3);
    census_kernel<<<grid, block>>>(x, out);
}